// round 13
// baseline (speedup 1.0000x reference)
#include <cuda_runtime.h>
#include <cuda_bf16.h>
#include <cstdint>
#include <math.h>

#define K_DIM 128
#define D_DIM 256
#define TILE_M 128
#define NTHREADS 256
#define SBB 528            // B smem row stride: conflict-free ldsm (16 mod 128)
#define BIMG (128 * SBB)   // 67584
#define SBA 80             // A substage row stride (64B payload + 16B pad; 80*k mod 128 distinct)
#define ASTG (128 * SBA)   // 10240 per substage
#define NBUF 4
#define CAP_ROWS 524288

// ---- dynamic smem layout (bytes) ----
#define SMEM_B     0
#define SMEM_A(b)  (BIMG + (b) * ASTG)          // 4 bufs: 67584..108544
#define SMEM_MISC  (BIMG + NBUF * ASTG)         // 108544
#define SMEM_C2    (SMEM_MISC + 0)
#define SMEM_X2    (SMEM_MISC + 512)
#define SMEM_BV    (SMEM_MISC + 1024)
#define SMEM_BS    (SMEM_MISC + 2048)
#define SMEM_BI    (SMEM_MISC + 3072)
#define SMEM_IDX   (SMEM_MISC + 4096)
#define SMEM_FCNT  (SMEM_MISC + 4608)
#define SMEM_FLIST (SMEM_MISC + 4612)
#define SMEM_TOTAL (SMEM_MISC + 5200)           // 113744 -> 2 CTAs/SM

__device__ float g_c2[K_DIM];
__device__ __align__(16) unsigned char g_B[BIMG];
__device__ __align__(16) unsigned char g_Abf[(size_t)CAP_ROWS * 512];
__device__ float g_x2[CAP_ROWS];

// ---------------- PTX helpers ----------------
__device__ __forceinline__ uint32_t smem_u32(const void* p) {
    uint32_t a;
    asm("{ .reg .u64 t; cvta.to.shared.u64 t, %1; cvt.u32.u64 %0, t; }"
        : "=r"(a) : "l"(p));
    return a;
}
__device__ __forceinline__ void ldsm4(uint32_t* r, uint32_t addr) {
    asm volatile("ldmatrix.sync.aligned.m8n8.x4.shared.b16 {%0,%1,%2,%3}, [%4];"
                 : "=r"(r[0]), "=r"(r[1]), "=r"(r[2]), "=r"(r[3]) : "r"(addr));
}
__device__ __forceinline__ void mma_bf16(float* d, const uint32_t* a, const uint32_t* b) {
    asm volatile("mma.sync.aligned.m16n8k16.row.col.f32.bf16.bf16.f32 "
                 "{%0,%1,%2,%3}, {%4,%5,%6,%7}, {%8,%9}, {%0,%1,%2,%3};"
                 : "+f"(d[0]), "+f"(d[1]), "+f"(d[2]), "+f"(d[3])
                 : "r"(a[0]), "r"(a[1]), "r"(a[2]), "r"(a[3]), "r"(b[0]), "r"(b[1]));
}
__device__ __forceinline__ void cp16(uint32_t smaddr, const void* gaddr) {
    asm volatile("cp.async.ca.shared.global [%0], [%1], 16;"
                 :: "r"(smaddr), "l"(gaddr) : "memory");
}
#define CP_COMMIT() asm volatile("cp.async.commit_group;" ::: "memory")
#define CP_WAIT(n)  asm volatile("cp.async.wait_group %0;" :: "n"(n) : "memory")

__device__ __forceinline__ uint32_t pack_bf2(float a, float b) {
    __nv_bfloat16 ha = __float2bfloat16_rn(a), hb = __float2bfloat16_rn(b);
    uint16_t ra = *reinterpret_cast<uint16_t*>(&ha);
    uint16_t rb = *reinterpret_cast<uint16_t*>(&hb);
    return (uint32_t)ra | ((uint32_t)rb << 16);
}

// ---------------- prep: block b -> c2[b] + B row b (528-stride image) ----------------
__global__ void prep_kernel(const float* __restrict__ C) {
    __shared__ float red[8];
    const int tid = threadIdx.x;
    const int b = blockIdx.x;
    float v = C[(size_t)b * D_DIM + tid];
    __nv_bfloat16 h = __float2bfloat16_rn(v);
    *reinterpret_cast<uint16_t*>(&g_B[b * SBB + tid * 2]) =
        *reinterpret_cast<uint16_t*>(&h);
    float s = v * v;
#pragma unroll
    for (int o = 16; o >= 1; o >>= 1) s += __shfl_xor_sync(0xffffffffu, s, o);
    if ((tid & 31) == 0) red[tid >> 5] = s;
    __syncthreads();
    if (tid == 0) {
        float t = 0.f;
#pragma unroll
        for (int w = 0; w < 8; ++w) t += red[w];
        g_c2[b] = t;
    }
}

// ---------------- convert: seq fp32 -> bf16 + per-row x2 (streaming) ----------------
__global__ __launch_bounds__(256, 8)
void convert_kernel(const float* __restrict__ seq, int N) {
    const int wid = threadIdx.x >> 5, lane = threadIdx.x & 31;
    const int row = blockIdx.x * 8 + wid;
    if (row >= N || row >= CAP_ROWS) return;
    const float* src = seq + (size_t)row * D_DIM;
    float4 v0 = *reinterpret_cast<const float4*>(src + lane * 4);
    float4 v1 = *reinterpret_cast<const float4*>(src + 128 + lane * 4);
    unsigned char* dst = g_Abf + (size_t)row * 512;
    *reinterpret_cast<uint2*>(dst + lane * 8) =
        make_uint2(pack_bf2(v0.x, v0.y), pack_bf2(v0.z, v0.w));
    *reinterpret_cast<uint2*>(dst + 256 + lane * 8) =
        make_uint2(pack_bf2(v1.x, v1.y), pack_bf2(v1.z, v1.w));
    float s = v0.x*v0.x + v0.y*v0.y + v0.z*v0.z + v0.w*v0.w
            + v1.x*v1.x + v1.y*v1.y + v1.z*v1.z + v1.w*v1.w;
#pragma unroll
    for (int o = 16; o >= 1; o >>= 1) s += __shfl_xor_sync(0xffffffffu, s, o);
    if (lane == 0) g_x2[row] = s;
}

// ---------------- main ----------------
__global__ __launch_bounds__(NTHREADS, 2)
void assign_kernel(const float* __restrict__ seq, const float* __restrict__ u,
                   const float* __restrict__ C, float* __restrict__ assign,
                   int N) {
    extern __shared__ char smem[];
    const uint32_t sm = smem_u32(smem);
    const int tid = threadIdx.x;
    const int wid = tid >> 5;
    const int lane = tid & 31;
    const int row0 = blockIdx.x * TILE_M;

    float* c2s = (float*)(smem + SMEM_C2);
    float* x2s = (float*)(smem + SMEM_X2);
    float* bvs = (float*)(smem + SMEM_BV);
    float* bss = (float*)(smem + SMEM_BS);
    int*   bis = (int*)(smem + SMEM_BI);
    int*   idxs = (int*)(smem + SMEM_IDX);
    int*   fcnt = (int*)(smem + SMEM_FCNT);
    int*   flist = (int*)(smem + SMEM_FLIST);

    // A substage copy: 512 cp16 = 2 per thread. row=idx>>2, c=idx&3.
#define CP_A(S) do {                                                             \
    int _buf = (S) & 3;                                                          \
    _Pragma("unroll")                                                            \
    for (int j = 0; j < 2; ++j) {                                                \
        int idx = tid + NTHREADS * j;                                            \
        int row = idx >> 2, c = idx & 3;                                         \
        int grow = row0 + row;                                                   \
        if (grow < N)                                                            \
            cp16(sm + SMEM_A(_buf) + (uint32_t)row * SBA + c * 16,               \
                 g_Abf + (size_t)grow * 512 + (S) * 64 + c * 16);                \
    }                                                                            \
} while (0)

    // ---- prologue: B blit (group), A substage 0 (group), A substage 1 (group) ----
#pragma unroll
    for (int j = 0; j < 17; ++j) {
        int off = (tid + NTHREADS * j) * 16;
        if (off < BIMG) cp16(sm + SMEM_B + off, g_B + off);
    }
    CP_COMMIT();
    CP_A(0); CP_COMMIT();
    CP_A(1); CP_COMMIT();
    if (tid < K_DIM) {
        c2s[tid] = g_c2[tid];
        int grow = row0 + tid;
        x2s[tid] = (grow < N) ? g_x2[grow] : 0.f;
    }
    if (tid == 0) *fcnt = 0;

    const int wr = wid >> 1;       // 0..3
    const int wc = wid & 1;        // 0..1
    const int rg = lane >> 2;
    const int tg = lane & 3;

    float acc[2][8][4];
#pragma unroll
    for (int mi = 0; mi < 2; mi++)
#pragma unroll
        for (int ni = 0; ni < 8; ni++)
#pragma unroll
            for (int j = 0; j < 4; j++) acc[mi][ni][j] = 0.f;

    const uint32_t a_lane_off =
        (uint32_t)(lane & 15) * SBA + (uint32_t)(lane >> 4) * 16;
    const uint32_t bBase = sm + SMEM_B +
        (uint32_t)(wc * 64 + (lane & 7) + ((lane >> 4) << 3)) * SBB +
        (uint32_t)(((lane >> 3) & 1) << 4);

    // ---- deep-pipelined mainloop over 8 substages (32 cols each) ----
#pragma unroll
    for (int s = 0; s < 8; ++s) {
        if (s + 2 < 8) CP_A(s + 2);    // 2-ahead into buf (s+2)&3: consumed at s-2, safe
        CP_COMMIT();                   // one group per iteration (possibly empty)
        CP_WAIT(2);                    // groups through substage s complete (B done at s=0)
        __syncthreads();

        const uint32_t aBase = sm + SMEM_A(s & 3);
#pragma unroll
        for (int kk = 0; kk < 2; ++kk) {
            uint32_t ah[2][4];
#pragma unroll
            for (int mi = 0; mi < 2; ++mi)
                ldsm4(ah[mi], aBase + (uint32_t)(wr * 32 + mi * 16) * SBA
                               + a_lane_off + (uint32_t)kk * 32);
            const uint32_t bk = bBase + (uint32_t)(s * 64 + kk * 32);
#pragma unroll
            for (int np = 0; np < 4; ++np) {
                uint32_t bh[4];
                ldsm4(bh, bk + (uint32_t)(np * 16) * SBB);
#pragma unroll
                for (int mi = 0; mi < 2; ++mi) {
                    mma_bf16(acc[mi][np * 2 + 0], ah[mi], bh + 0);
                    mma_bf16(acc[mi][np * 2 + 1], ah[mi], bh + 2);
                }
            }
        }
    }
    __syncthreads();

    // ---- epilogue: logits (fast log), per-row top-2, argmax ----
#pragma unroll
    for (int mi = 0; mi < 2; ++mi) {
#pragma unroll
        for (int half = 0; half < 2; ++half) {
            int row = wr * 32 + mi * 16 + rg + 8 * half;
            int grow = row0 + row;
            float x2r = x2s[row];
            const float* urow = u + (size_t)(grow < N ? grow : 0) * K_DIM + wc * 64;
            float best = -INFINITY, second = -INFINITY;
            int bidx = 0;
#pragma unroll
            for (int ni = 0; ni < 8; ++ni) {
                int col = ni * 8 + tg * 2;
                float2 uu = *reinterpret_cast<const float2*>(urow + col);
#pragma unroll
                for (int j = 0; j < 2; ++j) {
                    int k = wc * 64 + col + j;
                    float dot = acc[mi][ni][2 * half + j];
                    float sq = fmaxf(x2r - 2.f * dot + c2s[k], 0.f);
                    float uv = j ? uu.y : uu.x;
                    float gb = -__logf(-__logf(uv + 1e-10f) + 1e-10f);
                    float lg = sqrtf(sq) + gb;
                    if (lg > best) { second = best; best = lg; bidx = k; }
                    else if (lg > second) { second = lg; }
                }
            }
#pragma unroll
            for (int o = 1; o <= 2; o <<= 1) {
                float b2 = __shfl_xor_sync(0xffffffffu, best, o);
                float s2 = __shfl_xor_sync(0xffffffffu, second, o);
                int i2 = __shfl_xor_sync(0xffffffffu, bidx, o);
                float lo = fminf(best, b2);
                if (b2 > best || (b2 == best && i2 < bidx)) {
                    second = fmaxf(lo, s2); best = b2; bidx = i2;
                } else {
                    second = fmaxf(lo, second);
                }
            }
            if (tg == 0) {
                bvs[wc * 128 + row] = best;
                bss[wc * 128 + row] = second;
                bis[wc * 128 + row] = bidx;
            }
        }
    }
    __syncthreads();

    // combine halves; flag near-ties
    if (tid < 128) {
        float v0 = bvs[tid], v1 = bvs[128 + tid];
        float s0 = bss[tid], s1 = bss[128 + tid];
        bool h1 = (v1 > v0);
        float ball = h1 ? v1 : v0;
        float sall = fmaxf(fminf(v0, v1), h1 ? s1 : s0);
        idxs[tid] = h1 ? bis[128 + tid] : bis[tid];
        if (row0 + tid < N && ball - sall < 4e-3f) {
            int p = atomicAdd(fcnt, 1);
            flist[p] = tid;
        }
    }
    __syncthreads();

    // ---- exact fp32 fallback ----
    int nf = *fcnt;
    for (int f = 0; f < nf; ++f) {
        int row = flist[f];
        int grow = row0 + row;
        {
            int k = tid & 127, h = tid >> 7;
            const float* xr = seq + (size_t)grow * D_DIM + h * 128;
            const float* cr = C + (size_t)k * D_DIM + h * 128;
            float p = 0.f;
#pragma unroll 8
            for (int d = 0; d < 128; ++d) p = fmaf(xr[d], cr[d], p);
            bvs[tid] = p;
        }
        __syncthreads();
        if (tid < 128) {
            float dot = bvs[tid] + bvs[tid + 128];
            float sq = fmaxf(x2s[row] - 2.f * dot + c2s[tid], 0.f);
            float uv = u[(size_t)grow * K_DIM + tid];
            bss[tid] = sqrtf(sq) - logf(-logf(uv + 1e-10f) + 1e-10f);
        }
        __syncthreads();
        if (tid == 0) {
            float bv = -INFINITY; int bi = 0;
            for (int k = 0; k < K_DIM; ++k)
                if (bss[k] > bv) { bv = bss[k]; bi = k; }
            idxs[row] = bi;
        }
        __syncthreads();
    }

    // ---- coalesced one-hot store ----
#pragma unroll
    for (int it = 0; it < 16; ++it) {
        int item = tid + NTHREADS * it;
        int row = item >> 5;
        int c4 = item & 31;
        int grow = row0 + row;
        if (grow < N) {
            int hot = idxs[row];
            float4 o = make_float4(0.f, 0.f, 0.f, 0.f);
            if ((hot >> 2) == c4) reinterpret_cast<float*>(&o)[hot & 3] = 1.0f;
            *reinterpret_cast<float4*>(assign + (size_t)grow * K_DIM + 4 * c4) = o;
        }
    }
}

extern "C" void kernel_launch(void* const* d_in, const int* in_sizes, int n_in,
                              void* d_out, int out_size) {
    const float* seq = (const float*)d_in[0];
    const float* u   = (const float*)d_in[1];
    const float* C   = (const float*)d_in[2];

    const int N = in_sizes[1] / K_DIM;
    float* out = (float*)d_out;
    float* assign = out;

    long long need_both = (long long)N * K_DIM + (long long)K_DIM * D_DIM;
    if ((long long)out_size >= need_both) {
        cudaMemcpyAsync(out, C, (size_t)K_DIM * D_DIM * sizeof(float),
                        cudaMemcpyDeviceToDevice);
        assign = out + K_DIM * D_DIM;
    }

    prep_kernel<<<128, 256>>>(C);
    convert_kernel<<<(N + 7) / 8, 256>>>(seq, N);

    cudaFuncSetAttribute(assign_kernel,
                         cudaFuncAttributeMaxDynamicSharedMemorySize, SMEM_TOTAL);
    int grid = (N + TILE_M - 1) / TILE_M;
    assign_kernel<<<grid, NTHREADS, SMEM_TOTAL>>>(seq, u, C, assign, N);
}

// round 14
// speedup vs baseline: 1.1086x; 1.1086x over previous
#include <cuda_runtime.h>
#include <cstdint>
#include <math.h>

#define K_DIM 128
#define D_DIM 256
#define NTHREADS 256
#define ROWS_PER_CTA 8

__device__ float g_c2[K_DIM];   // ||c_k||^2
__device__ float g_b2[K_DIM];   // 2*||c_k||

// ---------------- prep: c2 + b2 ----------------
__global__ void prep_kernel(const float* __restrict__ C) {
    int k = threadIdx.x;  // 128 threads
    float s = 0.f;
    const float* row = C + (size_t)k * D_DIM;
#pragma unroll 8
    for (int d = 0; d < D_DIM; ++d) s = fmaf(row[d], row[d], s);
    g_c2[k] = s;
    g_b2[k] = 2.0f * sqrtf(s);
}

__device__ __forceinline__ float warp_sum(float p) {
#pragma unroll
    for (int o = 16; o >= 1; o >>= 1) p += __shfl_xor_sync(0xffffffffu, p, o);
    return p;
}

// ---------------- main: one warp per row, candidate-pruned argmax ----------------
__global__ __launch_bounds__(NTHREADS)
void assign_kernel(const float* __restrict__ seq, const float* __restrict__ u,
                   const float* __restrict__ C, float* __restrict__ assign,
                   int N) {
    __shared__ float c2s[K_DIM];
    __shared__ float b2s[K_DIM];
    const int tid = threadIdx.x;
    const int warp = tid >> 5;
    const int lane = tid & 31;

    if (tid < K_DIM) { c2s[tid] = g_c2[tid]; b2s[tid] = g_b2[tid]; }
    __syncthreads();

    const int row = blockIdx.x * ROWS_PER_CTA + warp;
    if (row >= N) return;

    // ---- loads (all coalesced): x row (2 float4/lane), u row (1 float4/lane) ----
    const float4* xr = reinterpret_cast<const float4*>(seq + (size_t)row * D_DIM);
    float4 xa = xr[lane];          // dims 4*lane   .. +3
    float4 xb = xr[32 + lane];     // dims 128+4*lane .. +3
    float4 uu = reinterpret_cast<const float4*>(u + (size_t)row * K_DIM)[lane];

    // ---- x2, xn ----
    float p = xa.x*xa.x + xa.y*xa.y + xa.z*xa.z + xa.w*xa.w
            + xb.x*xb.x + xb.y*xb.y + xb.z*xb.z + xb.w*xb.w;
    const float x2 = warp_sum(p);
    const float xn = sqrtf(x2) * 1.000001f + 1e-6f;   // inflated upper bound of ||x||

    // ---- fast gumbel for this lane's 4 k's (k = 4*lane + q) ----
    float gq[4];
    gq[0] = -__logf(-__logf(uu.x + 1e-10f) + 1e-10f);
    gq[1] = -__logf(-__logf(uu.y + 1e-10f) + 1e-10f);
    gq[2] = -__logf(-__logf(uu.z + 1e-10f) + 1e-10f);
    gq[3] = -__logf(-__logf(uu.w + 1e-10f) + 1e-10f);

    // ---- score bounds per k; M = max_k (g~ + s_lo) ----
    float4 c2v = reinterpret_cast<const float4*>(c2s)[lane];
    float4 b2v = reinterpret_cast<const float4*>(b2s)[lane];
    float shi[4];
    float M = -INFINITY;
#pragma unroll
    for (int q = 0; q < 4; ++q) {
        float base = x2 + (&c2v.x)[q];
        float w = xn * (&b2v.x)[q];
        shi[q] = sqrtf(base + w);
        float slo = sqrtf(fmaxf(base - w, 0.f));
        M = fmaxf(M, gq[q] + slo);
    }
#pragma unroll
    for (int o = 16; o >= 1; o >>= 1)
        M = fmaxf(M, __shfl_xor_sync(0xffffffffu, M, o));

    // ---- candidate mask: guaranteed superset of argmax (margin >> fast-log err) ----
    unsigned qualm = 0;
#pragma unroll
    for (int q = 0; q < 4; ++q)
        if (gq[q] + shi[q] + 3e-3f >= M) qualm |= (1u << q);

    const float4* C4 = reinterpret_cast<const float4*>(C);
    float best = -INFINITY, second = -INFINITY;
    int bidx = 0;

    unsigned act = __ballot_sync(0xffffffffu, qualm != 0);
    while (act) {
        int l = __ffs(act) - 1;
        act &= act - 1;
        unsigned qm = __shfl_sync(0xffffffffu, qualm, l);
#pragma unroll
        for (int q = 0; q < 4; ++q) {
            if (qm & (1u << q)) {
                int k = l * 4 + q;
                float4 ca = C4[(size_t)k * 64 + lane];
                float4 cb = C4[(size_t)k * 64 + 32 + lane];
                float d = fmaf(xa.x, ca.x, fmaf(xa.y, ca.y, fmaf(xa.z, ca.z,
                          fmaf(xa.w, ca.w, fmaf(xb.x, cb.x, fmaf(xb.y, cb.y,
                          fmaf(xb.z, cb.z, xb.w * cb.w)))))));
                d = warp_sum(d);
                float sq = fmaxf(x2 - 2.f * d + c2s[k], 0.f);
                float gk = __shfl_sync(0xffffffffu, gq[q], l);
                float lg = sqrtf(sq) + gk;
                if (lg > best) { second = best; best = lg; bidx = k; }
                else if (lg > second) { second = lg; }
            }
        }
    }

    // ---- precision escape: redo candidates with precise logf (rare, warp-uniform) ----
    if (best - second < 2e-3f) {
        best = -INFINITY; second = -INFINITY; bidx = 0;
        unsigned act2 = __ballot_sync(0xffffffffu, qualm != 0);
        while (act2) {
            int l = __ffs(act2) - 1;
            act2 &= act2 - 1;
            unsigned qm = __shfl_sync(0xffffffffu, qualm, l);
#pragma unroll
            for (int q = 0; q < 4; ++q) {
                if (qm & (1u << q)) {
                    int k = l * 4 + q;
                    float4 ca = C4[(size_t)k * 64 + lane];
                    float4 cb = C4[(size_t)k * 64 + 32 + lane];
                    float d = fmaf(xa.x, ca.x, fmaf(xa.y, ca.y, fmaf(xa.z, ca.z,
                              fmaf(xa.w, ca.w, fmaf(xb.x, cb.x, fmaf(xb.y, cb.y,
                              fmaf(xb.z, cb.z, xb.w * cb.w)))))));
                    d = warp_sum(d);
                    float sq = fmaxf(x2 - 2.f * d + c2s[k], 0.f);
                    float uk = __shfl_sync(0xffffffffu, (&uu.x)[q], l);
                    float gk = -logf(-logf(uk + 1e-10f) + 1e-10f);
                    float lg = sqrtf(sq) + gk;
                    if (lg > best || (lg == best && k < bidx)) {
                        second = best; best = lg; bidx = k;
                    } else if (lg > second) { second = lg; }
                }
            }
        }
    }

    // ---- one-hot row (coalesced float4) ----
    float4 o = make_float4(0.f, 0.f, 0.f, 0.f);
    if ((bidx >> 2) == lane) (&o.x)[bidx & 3] = 1.0f;
    reinterpret_cast<float4*>(assign + (size_t)row * K_DIM)[lane] = o;
}

extern "C" void kernel_launch(void* const* d_in, const int* in_sizes, int n_in,
                              void* d_out, int out_size) {
    const float* seq = (const float*)d_in[0];  // [N,256]
    const float* u   = (const float*)d_in[1];  // [N,128]
    const float* C   = (const float*)d_in[2];  // [128,256]

    const int N = in_sizes[1] / K_DIM;
    float* out = (float*)d_out;
    float* assign = out;

    long long need_both = (long long)N * K_DIM + (long long)K_DIM * D_DIM;
    if ((long long)out_size >= need_both) {
        cudaMemcpyAsync(out, C, (size_t)K_DIM * D_DIM * sizeof(float),
                        cudaMemcpyDeviceToDevice);
        assign = out + K_DIM * D_DIM;
    }

    prep_kernel<<<1, K_DIM>>>(C);

    int grid = (N + ROWS_PER_CTA - 1) / ROWS_PER_CTA;
    assign_kernel<<<grid, NTHREADS>>>(seq, u, C, assign, N);
}

// round 15
// speedup vs baseline: 2.1880x; 1.9737x over previous
#include <cuda_runtime.h>
#include <cstdint>
#include <math.h>

#define K_DIM 128
#define D_DIM 256
#define NTHREADS 256
#define ROWS_PER_CTA 8

__device__ float g_c2[K_DIM];   // ||c_k||^2
__device__ float g_b2[K_DIM];   // 2*||c_k||

// ---------------- prep: c2 + b2 ----------------
__global__ void prep_kernel(const float* __restrict__ C) {
    int k = threadIdx.x;  // 128 threads
    float s = 0.f;
    const float* row = C + (size_t)k * D_DIM;
#pragma unroll 8
    for (int d = 0; d < D_DIM; ++d) s = fmaf(row[d], row[d], s);
    g_c2[k] = s;
    g_b2[k] = 2.0f * sqrtf(s);
}

__device__ __forceinline__ float warp_sum(float p) {
#pragma unroll
    for (int o = 16; o >= 1; o >>= 1) p += __shfl_xor_sync(0xffffffffu, p, o);
    return p;
}

// ---------------- main: one warp per row, anchor-pruned argmax ----------------
__global__ __launch_bounds__(NTHREADS)
void assign_kernel(const float* __restrict__ seq, const float* __restrict__ u,
                   const float* __restrict__ C, float* __restrict__ assign,
                   int N) {
    const int lane = threadIdx.x & 31;
    const int row = blockIdx.x * ROWS_PER_CTA + (threadIdx.x >> 5);
    if (row >= N) return;

    // ---- coalesced loads: x row (2 float4/lane), u row, c2/b2 (L1-hot) ----
    const float4* xr = reinterpret_cast<const float4*>(seq + (size_t)row * D_DIM);
    float4 xa = xr[lane];
    float4 xb = xr[32 + lane];
    float4 uu = reinterpret_cast<const float4*>(u + (size_t)row * K_DIM)[lane];
    float4 c2v = __ldg(&reinterpret_cast<const float4*>(g_c2)[lane]);
    float4 b2v = __ldg(&reinterpret_cast<const float4*>(g_b2)[lane]);

    // ---- x2, xn ----
    float p = xa.x*xa.x + xa.y*xa.y + xa.z*xa.z + xa.w*xa.w
            + xb.x*xb.x + xb.y*xb.y + xb.z*xb.z + xb.w*xb.w;
    const float x2 = warp_sum(p);
    const float xn = sqrtf(x2) * 1.000001f + 1e-6f;   // upper bound of ||x||

    // ---- fast gumbel for this lane's 4 k's ----
    float gq[4];
    gq[0] = -__logf(-__logf(uu.x + 1e-10f) + 1e-10f);
    gq[1] = -__logf(-__logf(uu.y + 1e-10f) + 1e-10f);
    gq[2] = -__logf(-__logf(uu.z + 1e-10f) + 1e-10f);
    gq[3] = -__logf(-__logf(uu.w + 1e-10f) + 1e-10f);

    // ---- upper bounds + packed argmax of (g~ + s_hi) ----
    float shi[4];
    int pk = 0;   // keys are ~[10,30] > 0: int compare is monotone; low 7 bits carry k
#pragma unroll
    for (int q = 0; q < 4; ++q) {
        float base = x2 + (&c2v.x)[q];
        shi[q] = sqrtf(base + xn * (&b2v.x)[q]);
        float key = gq[q] + shi[q];
        int pq = (__float_as_int(key) & ~127) | (lane * 4 + q);
        pk = max(pk, pq);
    }
#pragma unroll
    for (int o = 16; o >= 1; o >>= 1)
        pk = max(pk, __shfl_xor_sync(0xffffffffu, pk, o));
    const int kstar = pk & 127;

    const float4* C4 = reinterpret_cast<const float4*>(C);

    // ---- anchor: exact logit of kstar ----
    float4 ca = C4[(size_t)kstar * 64 + lane];
    float4 cb = C4[(size_t)kstar * 64 + 32 + lane];
    float d = fmaf(xa.x, ca.x, fmaf(xa.y, ca.y, fmaf(xa.z, ca.z,
              fmaf(xa.w, ca.w, fmaf(xb.x, cb.x, fmaf(xb.y, cb.y,
              fmaf(xb.z, cb.z, xb.w * cb.w)))))));
    d = warp_sum(d);
    float c2k = __shfl_sync(0xffffffffu, (&c2v.x)[kstar & 3], kstar >> 2);
    float gk0 = __shfl_sync(0xffffffffu, gq[kstar & 3], kstar >> 2);
    float best = sqrtf(fmaxf(x2 - 2.f * d + c2k, 0.f)) + gk0;
    float second = -INFINITY;
    int bidx = kstar;

    // ---- candidates vs realized anchor (sound: margin covers fast-log + fp err) ----
    unsigned qualm = 0;
#pragma unroll
    for (int q = 0; q < 4; ++q)
        if (gq[q] + shi[q] + 3e-3f >= best && (lane * 4 + q) != kstar)
            qualm |= (1u << q);

    unsigned act = __ballot_sync(0xffffffffu, qualm != 0);
    while (act) {
        int l = __ffs(act) - 1;
        act &= act - 1;
        unsigned qm = __shfl_sync(0xffffffffu, qualm, l);
#pragma unroll
        for (int q = 0; q < 4; ++q) {
            if (qm & (1u << q)) {
                int k = l * 4 + q;
                float4 ka = C4[(size_t)k * 64 + lane];
                float4 kb = C4[(size_t)k * 64 + 32 + lane];
                float dd = fmaf(xa.x, ka.x, fmaf(xa.y, ka.y, fmaf(xa.z, ka.z,
                           fmaf(xa.w, ka.w, fmaf(xb.x, kb.x, fmaf(xb.y, kb.y,
                           fmaf(xb.z, kb.z, xb.w * kb.w)))))));
                dd = warp_sum(dd);
                float c2c = __shfl_sync(0xffffffffu, (&c2v.x)[q], l);
                float gg = __shfl_sync(0xffffffffu, gq[q], l);
                float lg = sqrtf(fmaxf(x2 - 2.f * dd + c2c, 0.f)) + gg;
                if (lg > best || (lg == best && k < bidx)) {
                    second = best; best = lg; bidx = k;
                } else if (lg > second) { second = lg; }
            }
        }
    }

    // ---- precision escape: precise logf over candidates + kstar (rare) ----
    if (best - second < 2e-3f) {
        unsigned qualm2 = qualm;
        if ((kstar >> 2) == lane) qualm2 |= (1u << (kstar & 3));
        best = -INFINITY; second = -INFINITY; bidx = 0;
        unsigned act2 = __ballot_sync(0xffffffffu, qualm2 != 0);
        while (act2) {
            int l = __ffs(act2) - 1;
            act2 &= act2 - 1;
            unsigned qm = __shfl_sync(0xffffffffu, qualm2, l);
#pragma unroll
            for (int q = 0; q < 4; ++q) {
                if (qm & (1u << q)) {
                    int k = l * 4 + q;
                    float4 ka = C4[(size_t)k * 64 + lane];
                    float4 kb = C4[(size_t)k * 64 + 32 + lane];
                    float dd = fmaf(xa.x, ka.x, fmaf(xa.y, ka.y, fmaf(xa.z, ka.z,
                               fmaf(xa.w, ka.w, fmaf(xb.x, kb.x, fmaf(xb.y, kb.y,
                               fmaf(xb.z, kb.z, xb.w * kb.w)))))));
                    dd = warp_sum(dd);
                    float c2c = __shfl_sync(0xffffffffu, (&c2v.x)[q], l);
                    float uk = __shfl_sync(0xffffffffu, (&uu.x)[q], l);
                    float gg = -logf(-logf(uk + 1e-10f) + 1e-10f);
                    float lg = sqrtf(fmaxf(x2 - 2.f * dd + c2c, 0.f)) + gg;
                    if (lg > best || (lg == best && k < bidx)) {
                        second = best; best = lg; bidx = k;
                    } else if (lg > second) { second = lg; }
                }
            }
        }
    }

    // ---- one-hot row (coalesced float4) ----
    float4 o = make_float4(0.f, 0.f, 0.f, 0.f);
    if ((bidx >> 2) == lane) (&o.x)[bidx & 3] = 1.0f;
    reinterpret_cast<float4*>(assign + (size_t)row * K_DIM)[lane] = o;
}

extern "C" void kernel_launch(void* const* d_in, const int* in_sizes, int n_in,
                              void* d_out, int out_size) {
    const float* seq = (const float*)d_in[0];  // [N,256]
    const float* u   = (const float*)d_in[1];  // [N,128]
    const float* C   = (const float*)d_in[2];  // [128,256]

    const int N = in_sizes[1] / K_DIM;
    float* out = (float*)d_out;
    float* assign = out;

    long long need_both = (long long)N * K_DIM + (long long)K_DIM * D_DIM;
    if ((long long)out_size >= need_both) {
        cudaMemcpyAsync(out, C, (size_t)K_DIM * D_DIM * sizeof(float),
                        cudaMemcpyDeviceToDevice);
        assign = out + K_DIM * D_DIM;
    }

    prep_kernel<<<1, K_DIM>>>(C);

    int grid = (N + ROWS_PER_CTA - 1) / ROWS_PER_CTA;
    assign_kernel<<<grid, NTHREADS>>>(seq, u, C, assign, N);
}